// round 8
// baseline (speedup 1.0000x reference)
#include <cuda_runtime.h>
#include <cuda_bf16.h>

// ---------------------------------------------------------------------------
// FullyConnectedTree collapses to an affine map:  out = x @ v + c
//   W_l = sigmoid(el_l / 3) * es_l ;  a_l = sigmoid(b_l)*3 - 1
//   v = W0 @ W1 @ W2  (64-vector) ;  c = a0@(W1@W2) + a1@W2 + a2 (scalar)
// prep fires its PDL trigger at kernel START so mv launches concurrently.
// The data dependency is a device flag (g_ready), NOT grid completion:
// mv front-issues its x loads, spins briefly on the flag, then computes.
// Replay-safe reset via completion counter in mv.
// ---------------------------------------------------------------------------

__device__ float g_v[64];
__device__ float g_c;
__device__ volatile int g_ready;   // 0 at module load; reset each launch
__device__ unsigned int g_done;    // completion counter for reset

__device__ __forceinline__ float sig(float x) {
    return 1.0f / (1.0f + __expf(-x));
}

__device__ __forceinline__ float4 wprod4(float4 l, float4 s, float inv_T) {
    float4 r;
    r.x = sig(l.x * inv_T) * s.x;
    r.y = sig(l.y * inv_T) * s.y;
    r.z = sig(l.z * inv_T) * s.z;
    r.w = sig(l.w * inv_T) * s.w;
    return r;
}

__global__ __launch_bounds__(1024)
void fct_prep_kernel(const float* __restrict__ el0,
                     const float* __restrict__ el1,
                     const float* __restrict__ el2,
                     const float* __restrict__ es0,
                     const float* __restrict__ es1,
                     const float* __restrict__ es2,
                     const float* __restrict__ b0,
                     const float* __restrict__ b1,
                     const float* __restrict__ b2) {
#if CUDART_VERSION >= 11080
    // Let the dependent mv grid launch NOW; the real dependency is g_ready.
    cudaTriggerProgrammaticLaunchCompletion();
#endif

    __shared__ float w0[4096];     // W0 = sig(el0/T)*es0
    __shared__ float w1[4096];     // W1
    __shared__ float w2[64];       // W2 column
    __shared__ float t[64];        // t = W1 @ w2
    __shared__ float part[64];     // partials for c

    const float inv_T = 1.0f / 3.0f;
    const int tid = threadIdx.x;   // 1024 threads

    // One float4 per thread per array; all loads issued before any compute
    // -> single DRAM round-trip for the whole 64 KB of weights.
    const float4 l0 = __ldg(reinterpret_cast<const float4*>(el0) + tid);
    const float4 s0 = __ldg(reinterpret_cast<const float4*>(es0) + tid);
    const float4 l1 = __ldg(reinterpret_cast<const float4*>(el1) + tid);
    const float4 s1 = __ldg(reinterpret_cast<const float4*>(es1) + tid);
    float4 e2l, e2s; float bb0 = 0.f, bb1 = 0.f, bb2 = 0.f;
    if (tid < 16) {
        e2l = __ldg(reinterpret_cast<const float4*>(el2) + tid);
        e2s = __ldg(reinterpret_cast<const float4*>(es2) + tid);
    }
    if (tid < 64) { bb0 = __ldg(b0 + tid); bb1 = __ldg(b1 + tid); }
    if (tid == 0) { bb2 = __ldg(b2); }

    reinterpret_cast<float4*>(w0)[tid] = wprod4(l0, s0, inv_T);
    reinterpret_cast<float4*>(w1)[tid] = wprod4(l1, s1, inv_T);
    if (tid < 16) {
        reinterpret_cast<float4*>(w2)[tid] = wprod4(e2l, e2s, inv_T);
    }
    __syncthreads();

    // t[i] = sum_j W1[i][j] * w2[j]
    if (tid < 64) {
        float ti = 0.0f;
        #pragma unroll 16
        for (int j = 0; j < 64; j++)
            ti = fmaf(w1[tid * 64 + j], w2[j], ti);
        t[tid] = ti;

        float a0 = sig(bb0) * 3.0f - 1.0f;
        float a1 = sig(bb1) * 3.0f - 1.0f;
        part[tid] = fmaf(a0, ti, a1 * w2[tid]);
    }
    __syncthreads();

    // v[i] = sum_j W0[i][j] * t[j]
    if (tid < 64) {
        float vi = 0.0f;
        #pragma unroll 16
        for (int j = 0; j < 64; j++)
            vi = fmaf(w0[tid * 64 + j], t[j], vi);
        g_v[tid] = vi;
    }
    if (tid == 0) {
        float c = sig(bb2) * 3.0f - 1.0f;
        #pragma unroll 16
        for (int j = 0; j < 64; j++) c += part[j];
        g_c = c;
    }

    // Publish: release fence then raise the flag.
    __threadfence();
    __syncthreads();
    if (tid == 0) {
        g_ready = 1;
        __threadfence();
    }
}

// ---------------------------------------------------------------------------
// Streaming mat-vec: 16 lanes per row, 1 float4 per lane per row, 4 rows per
// lane-group. x loads issued first; then a brief flag spin (thread 0 only,
// nanosleep backoff) replaces the grid-completion wait.
// ---------------------------------------------------------------------------
static constexpr int RPG = 4;        // rows per 16-lane group
static constexpr int TPB = 256;

__global__ __launch_bounds__(TPB)
void fct_mv_kernel(const float* __restrict__ x,
                   float* __restrict__ out,
                   int B) {
    const int tid    = blockIdx.x * TPB + threadIdx.x;
    const int group  = tid >> 4;
    const int lane16 = tid & 15;
    const long long row0 = (long long)group * RPG;
    if (row0 >= B) return;   // never taken for exact grid

    // Issue the DRAM loads first — independent of prep's output.
    float4 xv[RPG];
    #pragma unroll
    for (int r = 0; r < RPG; r++) {
        xv[r] = __ldg(reinterpret_cast<const float4*>(x + (row0 + r) * 64) + lane16);
    }

    // Wait for the weight fold (loads above are already in flight).
    if (threadIdx.x == 0) {
        if (g_ready == 0) {
            while (g_ready == 0) { __nanosleep(64); }
        }
        __threadfence();   // acquire
    }
    __syncthreads();

    const float4 v4 = reinterpret_cast<const float4*>(g_v)[lane16];
    const float  c  = g_c;

    float acc[RPG];
    #pragma unroll
    for (int r = 0; r < RPG; r++) {
        float s = xv[r].x * v4.x;
        s = fmaf(xv[r].y, v4.y, s);
        s = fmaf(xv[r].z, v4.z, s);
        s = fmaf(xv[r].w, v4.w, s);
        acc[r] = s;
    }

    #pragma unroll
    for (int r = 0; r < RPG; r++) {
        float s = acc[r];
        s += __shfl_xor_sync(0xffffffffu, s, 8);
        s += __shfl_xor_sync(0xffffffffu, s, 4);
        s += __shfl_xor_sync(0xffffffffu, s, 2);
        s += __shfl_xor_sync(0xffffffffu, s, 1);
        if (lane16 == 0) {
            out[row0 + r] = s + c;
        }
    }

    // Replay-safe reset: last block to finish zeroes flag + counter.
    // (Every block increments only AFTER passing the spin, so no race.)
    if (threadIdx.x == 0) {
        unsigned int prev = atomicAdd(&g_done, 1u);
        if (prev == gridDim.x - 1) {
            g_done = 0u;
            g_ready = 0;
            __threadfence();
        }
    }
}

extern "C" void kernel_launch(void* const* d_in, const int* in_sizes, int n_in,
                              void* d_out, int out_size) {
    const float* x   = (const float*)d_in[0];
    const float* el0 = (const float*)d_in[1];
    const float* el1 = (const float*)d_in[2];
    const float* el2 = (const float*)d_in[3];
    const float* es0 = (const float*)d_in[4];
    const float* es1 = (const float*)d_in[5];
    const float* es2 = (const float*)d_in[6];
    const float* b0  = (const float*)d_in[7];
    const float* b1  = (const float*)d_in[8];
    const float* b2  = (const float*)d_in[9];
    float* out = (float*)d_out;

    const int B = out_size;   // 1048576 rows, 64 cols each

    fct_prep_kernel<<<1, 1024>>>(el0, el1, el2, es0, es1, es2, b0, b1, b2);

    const long long groups  = (B + RPG - 1) / RPG;
    const long long threads = groups * 16;
    const int blocks = (int)((threads + TPB - 1) / TPB);

#if CUDART_VERSION >= 11080
    // PDL launch: mv begins (and issues x loads) while prep is still running;
    // the g_ready flag is the only synchronization with prep's output.
    cudaLaunchConfig_t cfg = {};
    cfg.gridDim  = dim3(blocks, 1, 1);
    cfg.blockDim = dim3(TPB, 1, 1);
    cudaLaunchAttribute attr[1];
    attr[0].id = cudaLaunchAttributeProgrammaticStreamSerialization;
    attr[0].val.programmaticStreamSerializationAllowed = 1;
    cfg.attrs = attr;
    cfg.numAttrs = 1;
    cudaLaunchKernelEx(&cfg, fct_mv_kernel, x, out, B);
#else
    fct_mv_kernel<<<blocks, TPB>>>(x, out, B);
#endif
}

// round 9
// speedup vs baseline: 1.1284x; 1.1284x over previous
#include <cuda_runtime.h>
#include <cuda_bf16.h>

// ---------------------------------------------------------------------------
// FullyConnectedTree collapses to an affine map:  out = x @ v + c
//   W_l = sigmoid(el_l / 3) * es_l ;  a_l = sigmoid(b_l)*3 - 1
//   v = W0 @ W1 @ W2  (64-vector) ;  c = a0@(W1@W2) + a1@W2 + a2 (scalar)
// prep folds weights into g_v/g_c. PDL trigger fires right AFTER prep's
// weight loads complete (post first __syncthreads), so mv's launch latency
// overlaps prep's compute-only fold — mv's x-load burst never contends with
// prep's weight loads, and prep is done before mv reaches its grid sync.
// ---------------------------------------------------------------------------

__device__ float g_v[64];
__device__ float g_c;

__device__ __forceinline__ float sig(float x) {
    return 1.0f / (1.0f + __expf(-x));
}

__device__ __forceinline__ float4 wprod4(float4 l, float4 s, float inv_T) {
    float4 r;
    r.x = sig(l.x * inv_T) * s.x;
    r.y = sig(l.y * inv_T) * s.y;
    r.z = sig(l.z * inv_T) * s.z;
    r.w = sig(l.w * inv_T) * s.w;
    return r;
}

__global__ __launch_bounds__(1024)
void fct_prep_kernel(const float* __restrict__ el0,
                     const float* __restrict__ el1,
                     const float* __restrict__ el2,
                     const float* __restrict__ es0,
                     const float* __restrict__ es1,
                     const float* __restrict__ es2,
                     const float* __restrict__ b0,
                     const float* __restrict__ b1,
                     const float* __restrict__ b2) {
    __shared__ float w0[4096];     // W0 = sig(el0/T)*es0
    __shared__ float w1[4096];     // W1
    __shared__ float w2[64];       // W2 column
    __shared__ float t[64];        // t = W1 @ w2
    __shared__ float part[64];     // partials for c

    const float inv_T = 1.0f / 3.0f;
    const int tid = threadIdx.x;   // 1024 threads

    // One float4 per thread per array; all loads issued before any compute
    // -> single DRAM round-trip for the whole 64 KB of weights.
    const float4 l0 = __ldg(reinterpret_cast<const float4*>(el0) + tid);
    const float4 s0 = __ldg(reinterpret_cast<const float4*>(es0) + tid);
    const float4 l1 = __ldg(reinterpret_cast<const float4*>(el1) + tid);
    const float4 s1 = __ldg(reinterpret_cast<const float4*>(es1) + tid);
    float4 e2l, e2s; float bb0 = 0.f, bb1 = 0.f, bb2 = 0.f;
    if (tid < 16) {
        e2l = __ldg(reinterpret_cast<const float4*>(el2) + tid);
        e2s = __ldg(reinterpret_cast<const float4*>(es2) + tid);
    }
    if (tid < 64) { bb0 = __ldg(b0 + tid); bb1 = __ldg(b1 + tid); }
    if (tid == 0) { bb2 = __ldg(b2); }

    reinterpret_cast<float4*>(w0)[tid] = wprod4(l0, s0, inv_T);
    reinterpret_cast<float4*>(w1)[tid] = wprod4(l1, s1, inv_T);
    if (tid < 16) {
        reinterpret_cast<float4*>(w2)[tid] = wprod4(e2l, e2s, inv_T);
    }
    __syncthreads();

#if CUDART_VERSION >= 11080
    // All DRAM traffic for this kernel is done (consumed into smem above).
    // Let mv's launch latency overlap the compute-only fold below.
    cudaTriggerProgrammaticLaunchCompletion();
#endif

    // t[i] = sum_j W1[i][j] * w2[j]
    if (tid < 64) {
        float ti = 0.0f;
        #pragma unroll 16
        for (int j = 0; j < 64; j++)
            ti = fmaf(w1[tid * 64 + j], w2[j], ti);
        t[tid] = ti;

        float a0 = sig(bb0) * 3.0f - 1.0f;
        float a1 = sig(bb1) * 3.0f - 1.0f;
        part[tid] = fmaf(a0, ti, a1 * w2[tid]);
    }
    __syncthreads();

    // v[i] = sum_j W0[i][j] * t[j]
    if (tid < 64) {
        float vi = 0.0f;
        #pragma unroll 16
        for (int j = 0; j < 64; j++)
            vi = fmaf(w0[tid * 64 + j], t[j], vi);
        g_v[tid] = vi;
    }
    if (tid == 0) {
        float c = sig(bb2) * 3.0f - 1.0f;
        #pragma unroll 16
        for (int j = 0; j < 64; j++) c += part[j];
        g_c = c;
    }

    // Make g_v/g_c globally visible before this grid completes.
    __threadfence();
}

// ---------------------------------------------------------------------------
// Streaming mat-vec (proven 41.6us / 83.5% DRAM): 16 lanes per row,
// 1 float4 per lane per row, 4 rows per lane-group. x loads issued BEFORE
// the PDL grid-dependency sync.
// ---------------------------------------------------------------------------
static constexpr int RPG = 4;        // rows per 16-lane group
static constexpr int TPB = 256;

__global__ __launch_bounds__(TPB)
void fct_mv_kernel(const float* __restrict__ x,
                   float* __restrict__ out,
                   int B) {
    const int tid    = blockIdx.x * TPB + threadIdx.x;
    const int group  = tid >> 4;
    const int lane16 = tid & 15;
    const long long row0 = (long long)group * RPG;
    if (row0 >= B) return;   // never taken for exact grid

    // Issue the DRAM loads first — independent of prep's output.
    float4 xv[RPG];
    #pragma unroll
    for (int r = 0; r < RPG; r++) {
        xv[r] = __ldg(reinterpret_cast<const float4*>(x + (row0 + r) * 64) + lane16);
    }

#if CUDART_VERSION >= 11080
    cudaGridDependencySynchronize();   // waits for prep full completion
#endif

    const float4 v4 = reinterpret_cast<const float4*>(g_v)[lane16];
    const float  c  = g_c;

    float acc[RPG];
    #pragma unroll
    for (int r = 0; r < RPG; r++) {
        float s = xv[r].x * v4.x;
        s = fmaf(xv[r].y, v4.y, s);
        s = fmaf(xv[r].z, v4.z, s);
        s = fmaf(xv[r].w, v4.w, s);
        acc[r] = s;
    }

    #pragma unroll
    for (int r = 0; r < RPG; r++) {
        float s = acc[r];
        s += __shfl_xor_sync(0xffffffffu, s, 8);
        s += __shfl_xor_sync(0xffffffffu, s, 4);
        s += __shfl_xor_sync(0xffffffffu, s, 2);
        s += __shfl_xor_sync(0xffffffffu, s, 1);
        if (lane16 == 0) {
            out[row0 + r] = s + c;
        }
    }
}

extern "C" void kernel_launch(void* const* d_in, const int* in_sizes, int n_in,
                              void* d_out, int out_size) {
    const float* x   = (const float*)d_in[0];
    const float* el0 = (const float*)d_in[1];
    const float* el1 = (const float*)d_in[2];
    const float* el2 = (const float*)d_in[3];
    const float* es0 = (const float*)d_in[4];
    const float* es1 = (const float*)d_in[5];
    const float* es2 = (const float*)d_in[6];
    const float* b0  = (const float*)d_in[7];
    const float* b1  = (const float*)d_in[8];
    const float* b2  = (const float*)d_in[9];
    float* out = (float*)d_out;

    const int B = out_size;   // 1048576 rows, 64 cols each

    fct_prep_kernel<<<1, 1024>>>(el0, el1, el2, es0, es1, es2, b0, b1, b2);

    const long long groups  = (B + RPG - 1) / RPG;
    const long long threads = groups * 16;
    const int blocks = (int)((threads + TPB - 1) / TPB);

#if CUDART_VERSION >= 11080
    // PDL launch: mv may begin (and issue x loads) once prep's loads are done.
    cudaLaunchConfig_t cfg = {};
    cfg.gridDim  = dim3(blocks, 1, 1);
    cfg.blockDim = dim3(TPB, 1, 1);
    cudaLaunchAttribute attr[1];
    attr[0].id = cudaLaunchAttributeProgrammaticStreamSerialization;
    attr[0].val.programmaticStreamSerializationAllowed = 1;
    cfg.attrs = attr;
    cfg.numAttrs = 1;
    cudaLaunchKernelEx(&cfg, fct_mv_kernel, x, out, B);
#else
    fct_mv_kernel<<<blocks, TPB>>>(x, out, B);
#endif
}